// round 13
// baseline (speedup 1.0000x reference)
#include <cuda_runtime.h>
#include <cuda_fp16.h>
#include <cstdint>

#define BSZ 4
#define SEQ 2048
#define DM 1024
#define NH 16
#define DH 64
#define MTOT (BSZ*SEQ)   // 8192

// ---------------- device scratch --------------------------------------------
__device__ __half g_xq[MTOT*DM];
__device__ __half g_xk[MTOT*DM];
__device__ __half g_xv[MTOT*DM];
__device__ __half g_wq[DM*DM];
__device__ __half g_wk[DM*DM];
__device__ __half g_wv[DM*DM];
__device__ __half g_wo[DM*DM];
__device__ __half g_q[MTOT*DM];   // (b,h,s,d) fp16, pre-scaled by log2e/8
__device__ __half g_k[MTOT*DM];
__device__ __half g_v[MTOT*DM];
__device__ __half g_ctx[MTOT*DM]; // (b,s,dmodel)

// ---------------- asm helpers -------------------------------------------------
__device__ __forceinline__ unsigned smem_u32(const void* p) {
    return (unsigned)__cvta_generic_to_shared(p);
}
__device__ __forceinline__ void cp_async16(void* smem, const void* gmem) {
    unsigned s = smem_u32(smem);
    asm volatile("cp.async.cg.shared.global [%0], [%1], 16;\n" :: "r"(s), "l"(gmem));
}
#define CP_COMMIT() asm volatile("cp.async.commit_group;\n" ::: "memory")
#define CP_WAIT0()  asm volatile("cp.async.wait_group 0;\n" ::: "memory")
#define CP_WAIT1()  asm volatile("cp.async.wait_group 1;\n" ::: "memory")

__device__ __forceinline__ void ldsm4(unsigned& r0, unsigned& r1, unsigned& r2,
                                      unsigned& r3, unsigned a) {
    asm volatile("ldmatrix.sync.aligned.m8n8.x4.shared.b16 {%0,%1,%2,%3}, [%4];"
                 : "=r"(r0), "=r"(r1), "=r"(r2), "=r"(r3) : "r"(a));
}
__device__ __forceinline__ void ldsm4t(unsigned& r0, unsigned& r1, unsigned& r2,
                                       unsigned& r3, unsigned a) {
    asm volatile("ldmatrix.sync.aligned.m8n8.x4.trans.shared.b16 {%0,%1,%2,%3}, [%4];"
                 : "=r"(r0), "=r"(r1), "=r"(r2), "=r"(r3) : "r"(a));
}
__device__ __forceinline__ void mma16816(float* d, const unsigned* a,
                                         const unsigned* b, const float* c) {
    asm volatile("mma.sync.aligned.m16n8k16.row.col.f32.f16.f16.f32 "
                 "{%0,%1,%2,%3}, {%4,%5,%6,%7}, {%8,%9}, {%10,%11,%12,%13};"
                 : "=f"(d[0]), "=f"(d[1]), "=f"(d[2]), "=f"(d[3])
                 : "r"(a[0]), "r"(a[1]), "r"(a[2]), "r"(a[3]),
                   "r"(b[0]), "r"(b[1]),
                   "f"(c[0]), "f"(c[1]), "f"(c[2]), "f"(c[3]));
}
__device__ __forceinline__ float ex2(float x) {
    float r; asm("ex2.approx.f32 %0, %1;" : "=f"(r) : "f"(x)); return r;
}

// ---------------- fp32 -> fp16 conversion ------------------------------------
__global__ void cvt_acts(const float4* __restrict__ q, const float4* __restrict__ k,
                         const float4* __restrict__ v) {
    const float4* src = (blockIdx.y == 0) ? q : (blockIdx.y == 1) ? k : v;
    __half2* dst = (blockIdx.y == 0) ? (__half2*)g_xq
                 : (blockIdx.y == 1) ? (__half2*)g_xk : (__half2*)g_xv;
    int i = blockIdx.x * blockDim.x + threadIdx.x;
    float4 f = src[i];
    dst[2*i]   = __floats2half2_rn(f.x, f.y);
    dst[2*i+1] = __floats2half2_rn(f.z, f.w);
}
__global__ void cvt_w(const float4* __restrict__ wq, const float4* __restrict__ wk,
                      const float4* __restrict__ wv, const float4* __restrict__ wo) {
    const float4* src = (blockIdx.y == 0) ? wq : (blockIdx.y == 1) ? wk
                      : (blockIdx.y == 2) ? wv : wo;
    __half2* dst = (blockIdx.y == 0) ? (__half2*)g_wq : (blockIdx.y == 1) ? (__half2*)g_wk
                 : (blockIdx.y == 2) ? (__half2*)g_wv : (__half2*)g_wo;
    int i = blockIdx.x * blockDim.x + threadIdx.x;
    float4 f = src[i];
    dst[2*i]   = __floats2half2_rn(f.x, f.y);
    dst[2*i+1] = __floats2half2_rn(f.z, f.w);
}

// ---------------- NT GEMM: 3-stage cp.async, 2 CTAs/SM (R11, unchanged) ------
#define GST 72
#define GSTG (128*GST)
#define NSTG 3
#define GEMM_SMEM_BYTES (2*NSTG*GSTG*2)   // 110592 B -> 2 CTAs/SM

__global__ __launch_bounds__(256, 2)
void gemm_nt(const float* __restrict__ b0, const float* __restrict__ b1,
             const float* __restrict__ b2, int mode, float* __restrict__ dstf)
{
    extern __shared__ __half smh[];
    __half* As = smh;
    __half* Bs = smh + NSTG*GSTG;

    const int z = blockIdx.z;
    const __half* __restrict__ A;
    const __half* __restrict__ B;
    const float* __restrict__ bias;
    __half* dsth;
    float scale;
    if (mode == 0) {
        A = (z == 0) ? g_xq : (z == 1) ? g_xk : g_xv;
        B = (z == 0) ? g_wq : (z == 1) ? g_wk : g_wv;
        bias = (z == 0) ? b0 : (z == 1) ? b1 : b2;
        dsth = (z == 0) ? g_q : (z == 1) ? g_k : g_v;
        scale = (z == 0) ? 0.125f * 1.44269504088896f : 1.0f;
    } else {
        A = g_ctx; B = g_wo; bias = b0; dsth = nullptr; scale = 1.0f;
    }

    const int tid  = threadIdx.x;
    const int w    = tid >> 5;
    const int lane = tid & 31;
    const int wr   = w >> 1;
    const int wc   = w & 1;
    const int m0   = blockIdx.y * 128;
    const int n0   = blockIdx.x * 128;

    float acc[2][8][4];
    #pragma unroll
    for (int mt = 0; mt < 2; mt++)
        #pragma unroll
        for (int i = 0; i < 8; i++)
            #pragma unroll
            for (int j = 0; j < 4; j++) acc[mt][i][j] = 0.0f;

    const int NCH = DM / 64;
    const int lrow = tid >> 3, lcol = (tid & 7) * 8;

    #pragma unroll
    for (int p = 0; p < 2; p++) {
        #pragma unroll
        for (int u = 0; u < 4; u++) {
            int row = lrow + u*32;
            cp_async16(As + p*GSTG + row*GST + lcol, A + (size_t)(m0+row)*DM + p*64 + lcol);
            cp_async16(Bs + p*GSTG + row*GST + lcol, B + (size_t)(n0+row)*DM + p*64 + lcol);
        }
        CP_COMMIT();
    }

    #pragma unroll 1
    for (int s = 0; s < NCH; s++) {
        const int st = s % NSTG;
        if (s + 1 < NCH) { CP_WAIT1(); } else { CP_WAIT0(); }
        __syncthreads();
        if (s + 2 < NCH) {
            const int nst = (s + 2) % NSTG;
            const int k0  = (s + 2) * 64;
            #pragma unroll
            for (int u = 0; u < 4; u++) {
                int row = lrow + u*32;
                cp_async16(As + nst*GSTG + row*GST + lcol,
                           A + (size_t)(m0+row)*DM + k0 + lcol);
                cp_async16(Bs + nst*GSTG + row*GST + lcol,
                           B + (size_t)(n0+row)*DM + k0 + lcol);
            }
            CP_COMMIT();
        }
        const __half* Ab = As + st*GSTG;
        const __half* Bb = Bs + st*GSTG;
        #pragma unroll
        for (int kk = 0; kk < 4; kk++) {
            unsigned af[2][4];
            #pragma unroll
            for (int mt = 0; mt < 2; mt++) {
                unsigned a = smem_u32(Ab + (wr*32 + mt*16 + (lane & 15))*GST
                                      + kk*16 + (lane >> 4)*8);
                ldsm4(af[mt][0], af[mt][1], af[mt][2], af[mt][3], a);
            }
            #pragma unroll
            for (int cp2 = 0; cp2 < 4; cp2++) {
                unsigned r0, r1, r2, r3;
                int row = wc*64 + cp2*16 + (lane >> 4)*8 + (lane & 7);
                int col = kk*16 + ((lane >> 3) & 1)*8;
                ldsm4(r0, r1, r2, r3, smem_u32(Bb + row*GST + col));
                unsigned bfa[2] = {r0, r1}, bfb[2] = {r2, r3};
                #pragma unroll
                for (int mt = 0; mt < 2; mt++) {
                    mma16816(acc[mt][2*cp2],     af[mt], bfa, acc[mt][2*cp2]);
                    mma16816(acc[mt][2*cp2 + 1], af[mt], bfb, acc[mt][2*cp2 + 1]);
                }
            }
        }
    }

    #pragma unroll
    for (int mt = 0; mt < 2; mt++) {
        int r0 = m0 + wr*32 + mt*16 + (lane >> 2);
        int r1 = r0 + 8;
        int b  = r0 >> 11;
        int sx0 = r0 & (SEQ-1), sx1 = r1 & (SEQ-1);
        #pragma unroll
        for (int c8 = 0; c8 < 8; c8++) {
            int col = n0 + wc*64 + c8*8 + 2*(lane & 3);
            float bia0 = bias[col], bia1 = bias[col+1];
            float v0 = (acc[mt][c8][0] + bia0) * scale;
            float v1 = (acc[mt][c8][1] + bia1) * scale;
            float v2 = (acc[mt][c8][2] + bia0) * scale;
            float v3 = (acc[mt][c8][3] + bia1) * scale;
            if (mode == 0) {
                int h = col >> 6, dh = col & (DH-1);
                __half2* p0 = (__half2*)&dsth[(size_t)((b*NH + h)*SEQ + sx0)*DH + dh];
                __half2* p1 = (__half2*)&dsth[(size_t)((b*NH + h)*SEQ + sx1)*DH + dh];
                *p0 = __floats2half2_rn(v0, v1);
                *p1 = __floats2half2_rn(v2, v3);
            } else {
                *(float2*)&dstf[(size_t)r0*DM + col] = make_float2(v0, v1);
                *(float2*)&dstf[(size_t)r1*DM + col] = make_float2(v2, v3);
            }
        }
    }
}

// ---------------- attention: 128 q-rows/CTA, 7-wave geometry ------------------
// grid (16, 64) = 1024 CTAs; dynamic smem padded >113.5KB forces 1 CTA/SM
// -> 1024/148 = 6.92 -> 7 waves, 98.8% wave efficiency (vs 86.5% at 512 CTAs).
// Chunk-pipelined fp32-ex2 softmax (R11 structure, single m-tile per warp).
#define TS 64
#define NT (SEQ/TS)              // 32
#define AST 72
#define QROWS 128
#define OFF_KS (QROWS*AST)
#define OFF_VS (OFF_KS + 2*TS*AST)
#define OFF_MSK (OFF_VS + 2*TS*AST)            // floats from here
#define ATT_SMEM_BYTES 120000                  // pad: needed ~56KB; >113.5KB -> 1 CTA/SM

__global__ __launch_bounds__(256, 1)
void attn_kernel(const int* __restrict__ mask)
{
    extern __shared__ __half smh[];
    __half* Qs = smh;
    __half* Ks = smh + OFF_KS;
    __half* Vs = smh + OFF_VS;
    float*  msk = (float*)(smh + OFF_MSK);

    const int tid  = threadIdx.x;
    const int w    = tid >> 5;
    const int lane = tid & 31;
    const int bh   = blockIdx.y;
    const int b    = bh >> 4;
    const int h    = bh & (NH-1);
    const int q0   = blockIdx.x * QROWS;

    const __half* qg  = g_q + (size_t)(bh*SEQ + q0) * DH;
    const __half* kgb = g_k + (size_t)bh * SEQ * DH;
    const __half* vgb = g_v + (size_t)bh * SEQ * DH;

    #pragma unroll
    for (int u = 0; u < 4; u++) {
        int c = tid + u*256;
        int row = c >> 3, col = (c & 7) * 8;
        cp_async16(Qs + row*AST + col, qg + row*DH + col);
    }
    #pragma unroll
    for (int u = 0; u < 2; u++) {
        int c = tid + u*256;
        int row = c >> 3, col = (c & 7) * 8;
        cp_async16(Ks + row*AST + col, kgb + row*DH + col);
        cp_async16(Vs + row*AST + col, vgb + row*DH + col);
    }
    CP_COMMIT();
    if (tid < 64) msk[tid] = (mask[b*SEQ + tid] != 0) ? 1.0f : 0.0f;

    CP_WAIT0();
    __syncthreads();

    unsigned qa[4][4];
    #pragma unroll
    for (int kd = 0; kd < 4; kd++) {
        unsigned a = smem_u32(Qs + (w*16 + (lane & 15))*AST + kd*16 + (lane >> 4)*8);
        ldsm4(qa[kd][0], qa[kd][1], qa[kd][2], qa[kd][3], a);
    }

    float oacc[8][4];
    #pragma unroll
    for (int i = 0; i < 8; i++)
        #pragma unroll
        for (int j = 0; j < 4; j++) oacc[i][j] = 0.0f;
    float run0 = 0.0f, run1 = 0.0f;

    const int ksrow = (lane >> 4)*8 + (lane & 7);
    const int kscol = ((lane >> 3) & 1)*8;

    #pragma unroll 1
    for (int t = 0; t < NT; t++) {
        const int buf = t & 1;
        if (t > 0) {
            CP_WAIT0();
            __syncthreads();
        }
        if (t + 1 < NT) {
            const int nb = buf ^ 1;
            const __half* kp = kgb + (size_t)(t+1)*TS*DH;
            const __half* vp = vgb + (size_t)(t+1)*TS*DH;
            #pragma unroll
            for (int u = 0; u < 2; u++) {
                int c = tid + u*256;
                int row = c >> 3, col = (c & 7) * 8;
                cp_async16(Ks + nb*TS*AST + row*AST + col, kp + row*DH + col);
                cp_async16(Vs + nb*TS*AST + row*AST + col, vp + row*DH + col);
            }
            CP_COMMIT();
            if (tid < 64)
                msk[nb*64 + tid] = (mask[b*SEQ + (t+1)*TS + tid] != 0) ? 1.0f : 0.0f;
        }

        const __half* Kb = Ks + buf*TS*AST;
        const __half* Vb = Vs + buf*TS*AST;
        const float*  mk = msk + buf*64;

        // double-buffered per-chunk score frags: scb[j&1][hh][4]
        float scb[2][2][4];

        // S(0)
        #pragma unroll
        for (int hh = 0; hh < 2; hh++)
            #pragma unroll
            for (int e = 0; e < 4; e++) scb[0][hh][e] = 0.0f;
        #pragma unroll
        for (int kd = 0; kd < 4; kd++) {
            unsigned r0, r1, r2, r3;
            ldsm4(r0, r1, r2, r3, smem_u32(Kb + ksrow*AST + kd*16 + kscol));
            unsigned bfa[2] = {r0, r1}, bfb[2] = {r2, r3};
            mma16816(scb[0][0], qa[kd], bfa, scb[0][0]);
            mma16816(scb[0][1], qa[kd], bfb, scb[0][1]);
        }

        #pragma unroll
        for (int j = 0; j < 4; j++) {
            const int cur = j & 1, nxt = cur ^ 1;
            // S(j+1) issued ahead of softmax(j)'s exp chain
            if (j < 3) {
                #pragma unroll
                for (int hh = 0; hh < 2; hh++)
                    #pragma unroll
                    for (int e = 0; e < 4; e++) scb[nxt][hh][e] = 0.0f;
                #pragma unroll
                for (int kd = 0; kd < 4; kd++) {
                    unsigned r0, r1, r2, r3;
                    ldsm4(r0, r1, r2, r3,
                          smem_u32(Kb + ((j+1)*16 + ksrow)*AST + kd*16 + kscol));
                    unsigned bfa[2] = {r0, r1}, bfb[2] = {r2, r3};
                    mma16816(scb[nxt][0], qa[kd], bfa, scb[nxt][0]);
                    mma16816(scb[nxt][1], qa[kd], bfb, scb[nxt][1]);
                }
            }

            // softmax(j)
            unsigned pa[4];
            #pragma unroll
            for (int hh = 0; hh < 2; hh++) {
                int c8 = 2*j + hh;
                float m0 = mk[c8*8 + 2*(lane & 3)];
                float m1 = mk[c8*8 + 2*(lane & 3) + 1];
                float p0 = ex2(scb[cur][hh][0]) * m0;
                float p1 = ex2(scb[cur][hh][1]) * m1;
                float p2 = ex2(scb[cur][hh][2]) * m0;
                float p3 = ex2(scb[cur][hh][3]) * m1;
                __half2 h01 = __floats2half2_rn(p0, p1);
                __half2 h23 = __floats2half2_rn(p2, p3);
                pa[hh*2    ] = *(unsigned*)&h01;
                pa[hh*2 + 1] = *(unsigned*)&h23;
                float2 f01 = __half22float2(h01);   // sum exactly what PV sees
                float2 f23 = __half22float2(h23);
                run0 += f01.x + f01.y;
                run1 += f23.x + f23.y;
            }

            // PV(j)
            #pragma unroll
            for (int cp2 = 0; cp2 < 4; cp2++) {
                unsigned r0, r1, r2, r3;
                int row = j*16 + (lane & 15);
                int col = cp2*16 + (lane >> 4)*8;
                ldsm4t(r0, r1, r2, r3, smem_u32(Vb + row*AST + col));
                unsigned bfa[2] = {r0, r1}, bfb[2] = {r2, r3};
                mma16816(oacc[2*cp2],     pa, bfa, oacc[2*cp2]);
                mma16816(oacc[2*cp2 + 1], pa, bfb, oacc[2*cp2 + 1]);
            }
        }
    }

    // quad-reduce rowsums, normalize + store
    run0 += __shfl_xor_sync(0xffffffffu, run0, 1);
    run0 += __shfl_xor_sync(0xffffffffu, run0, 2);
    run1 += __shfl_xor_sync(0xffffffffu, run1, 1);
    run1 += __shfl_xor_sync(0xffffffffu, run1, 2);

    float inv0 = 1.0f / run0, inv1 = 1.0f / run1;
    int r0 = q0 + w*16 + (lane >> 2);
    int r1 = r0 + 8;
    __half* base0 = g_ctx + (size_t)(b*SEQ + r0)*DM + h*DH;
    __half* base1 = g_ctx + (size_t)(b*SEQ + r1)*DM + h*DH;
    #pragma unroll
    for (int c8 = 0; c8 < 8; c8++) {
        int col = c8*8 + 2*(lane & 3);
        __half2 v01 = __floats2half2_rn(oacc[c8][0]*inv0, oacc[c8][1]*inv0);
        __half2 v23 = __floats2half2_rn(oacc[c8][2]*inv1, oacc[c8][3]*inv1);
        *(__half2*)(base0 + col) = v01;
        *(__half2*)(base1 + col) = v23;
    }
}

// ---------------- launch ------------------------------------------------------
extern "C" void kernel_launch(void* const* d_in, const int* in_sizes, int n_in,
                              void* d_out, int out_size)
{
    const float* Q    = (const float*)d_in[0];
    const float* K    = (const float*)d_in[1];
    const float* V    = (const float*)d_in[2];
    const int*   mask = (const int*)  d_in[3];
    const float* bq   = (const float*)d_in[5];
    const float* bk   = (const float*)d_in[7];
    const float* bv   = (const float*)d_in[9];
    const float* bo   = (const float*)d_in[11];

    cudaFuncSetAttribute(gemm_nt, cudaFuncAttributeMaxDynamicSharedMemorySize,
                         GEMM_SMEM_BYTES);
    cudaFuncSetAttribute(attn_kernel, cudaFuncAttributeMaxDynamicSharedMemorySize,
                         ATT_SMEM_BYTES);

    cvt_acts<<<dim3(MTOT*DM/4/256, 3), 256>>>((const float4*)Q, (const float4*)K,
                                              (const float4*)V);
    cvt_w<<<dim3(DM*DM/4/256, 4), 256>>>((const float4*)d_in[4], (const float4*)d_in[6],
                                         (const float4*)d_in[8], (const float4*)d_in[10]);

    gemm_nt<<<dim3(DM/128, MTOT/128, 3), 256, GEMM_SMEM_BYTES>>>(bq, bk, bv, 0, nullptr);

    attn_kernel<<<dim3(SEQ/QROWS, BSZ*NH), 256, ATT_SMEM_BYTES>>>(mask);

    gemm_nt<<<dim3(DM/128, MTOT/128, 1), 256, GEMM_SMEM_BYTES>>>(bo, nullptr, nullptr,
                                                                 1, (float*)d_out);
}

// round 14
// speedup vs baseline: 1.0267x; 1.0267x over previous
#include <cuda_runtime.h>
#include <cuda_fp16.h>
#include <cstdint>

#define BSZ 4
#define SEQ 2048
#define DM 1024
#define NH 16
#define DH 64
#define MTOT (BSZ*SEQ)   // 8192

// ---------------- device scratch --------------------------------------------
__device__ __half g_xq[MTOT*DM];
__device__ __half g_xk[MTOT*DM];
__device__ __half g_xv[MTOT*DM];
__device__ __half g_wq[DM*DM];
__device__ __half g_wk[DM*DM];
__device__ __half g_wv[DM*DM];
__device__ __half g_wo[DM*DM];
__device__ __half g_q[MTOT*DM];   // (b,h,s,d) fp16, pre-scaled by log2e/8
__device__ __half g_k[MTOT*DM];
__device__ __half g_v[MTOT*DM];
__device__ __half g_ctx[MTOT*DM]; // (b,s,dmodel)

// ---------------- asm helpers -------------------------------------------------
__device__ __forceinline__ unsigned smem_u32(const void* p) {
    return (unsigned)__cvta_generic_to_shared(p);
}
__device__ __forceinline__ void cp_async16(void* smem, const void* gmem) {
    unsigned s = smem_u32(smem);
    asm volatile("cp.async.cg.shared.global [%0], [%1], 16;\n" :: "r"(s), "l"(gmem));
}
#define CP_COMMIT() asm volatile("cp.async.commit_group;\n" ::: "memory")
#define CP_WAIT0()  asm volatile("cp.async.wait_group 0;\n" ::: "memory")
#define CP_WAIT1()  asm volatile("cp.async.wait_group 1;\n" ::: "memory")
#define BAR_SYNC(id) asm volatile("bar.sync %0, 128;" :: "r"(id) : "memory")

__device__ __forceinline__ void ldsm4(unsigned& r0, unsigned& r1, unsigned& r2,
                                      unsigned& r3, unsigned a) {
    asm volatile("ldmatrix.sync.aligned.m8n8.x4.shared.b16 {%0,%1,%2,%3}, [%4];"
                 : "=r"(r0), "=r"(r1), "=r"(r2), "=r"(r3) : "r"(a));
}
__device__ __forceinline__ void ldsm4t(unsigned& r0, unsigned& r1, unsigned& r2,
                                       unsigned& r3, unsigned a) {
    asm volatile("ldmatrix.sync.aligned.m8n8.x4.trans.shared.b16 {%0,%1,%2,%3}, [%4];"
                 : "=r"(r0), "=r"(r1), "=r"(r2), "=r"(r3) : "r"(a));
}
__device__ __forceinline__ void mma16816(float* d, const unsigned* a,
                                         const unsigned* b, const float* c) {
    asm volatile("mma.sync.aligned.m16n8k16.row.col.f32.f16.f16.f32 "
                 "{%0,%1,%2,%3}, {%4,%5,%6,%7}, {%8,%9}, {%10,%11,%12,%13};"
                 : "=f"(d[0]), "=f"(d[1]), "=f"(d[2]), "=f"(d[3])
                 : "r"(a[0]), "r"(a[1]), "r"(a[2]), "r"(a[3]),
                   "r"(b[0]), "r"(b[1]),
                   "f"(c[0]), "f"(c[1]), "f"(c[2]), "f"(c[3]));
}
__device__ __forceinline__ float ex2(float x) {
    float r; asm("ex2.approx.f32 %0, %1;" : "=f"(r) : "f"(x)); return r;
}

// ---------------- fp32 -> fp16 conversion ------------------------------------
__global__ void cvt_acts(const float4* __restrict__ q, const float4* __restrict__ k,
                         const float4* __restrict__ v) {
    const float4* src = (blockIdx.y == 0) ? q : (blockIdx.y == 1) ? k : v;
    __half2* dst = (blockIdx.y == 0) ? (__half2*)g_xq
                 : (blockIdx.y == 1) ? (__half2*)g_xk : (__half2*)g_xv;
    int i = blockIdx.x * blockDim.x + threadIdx.x;
    float4 f = src[i];
    dst[2*i]   = __floats2half2_rn(f.x, f.y);
    dst[2*i+1] = __floats2half2_rn(f.z, f.w);
}
__global__ void cvt_w(const float4* __restrict__ wq, const float4* __restrict__ wk,
                      const float4* __restrict__ wv, const float4* __restrict__ wo) {
    const float4* src = (blockIdx.y == 0) ? wq : (blockIdx.y == 1) ? wk
                      : (blockIdx.y == 2) ? wv : wo;
    __half2* dst = (blockIdx.y == 0) ? (__half2*)g_wq : (blockIdx.y == 1) ? (__half2*)g_wk
                 : (blockIdx.y == 2) ? (__half2*)g_wv : (__half2*)g_wo;
    int i = blockIdx.x * blockDim.x + threadIdx.x;
    float4 f = src[i];
    dst[2*i]   = __floats2half2_rn(f.x, f.y);
    dst[2*i+1] = __floats2half2_rn(f.z, f.w);
}

// ---------------- NT GEMM: 3-stage cp.async, 2 CTAs/SM (R11, unchanged) ------
#define GST 72
#define GSTG (128*GST)
#define NSTG 3
#define GEMM_SMEM_BYTES (2*NSTG*GSTG*2)   // 110592 B -> 2 CTAs/SM

__global__ __launch_bounds__(256, 2)
void gemm_nt(const float* __restrict__ b0, const float* __restrict__ b1,
             const float* __restrict__ b2, int mode, float* __restrict__ dstf)
{
    extern __shared__ __half smh[];
    __half* As = smh;
    __half* Bs = smh + NSTG*GSTG;

    const int z = blockIdx.z;
    const __half* __restrict__ A;
    const __half* __restrict__ B;
    const float* __restrict__ bias;
    __half* dsth;
    float scale;
    if (mode == 0) {
        A = (z == 0) ? g_xq : (z == 1) ? g_xk : g_xv;
        B = (z == 0) ? g_wq : (z == 1) ? g_wk : g_wv;
        bias = (z == 0) ? b0 : (z == 1) ? b1 : b2;
        dsth = (z == 0) ? g_q : (z == 1) ? g_k : g_v;
        scale = (z == 0) ? 0.125f * 1.44269504088896f : 1.0f;
    } else {
        A = g_ctx; B = g_wo; bias = b0; dsth = nullptr; scale = 1.0f;
    }

    const int tid  = threadIdx.x;
    const int w    = tid >> 5;
    const int lane = tid & 31;
    const int wr   = w >> 1;
    const int wc   = w & 1;
    const int m0   = blockIdx.y * 128;
    const int n0   = blockIdx.x * 128;

    float acc[2][8][4];
    #pragma unroll
    for (int mt = 0; mt < 2; mt++)
        #pragma unroll
        for (int i = 0; i < 8; i++)
            #pragma unroll
            for (int j = 0; j < 4; j++) acc[mt][i][j] = 0.0f;

    const int NCH = DM / 64;
    const int lrow = tid >> 3, lcol = (tid & 7) * 8;

    #pragma unroll
    for (int p = 0; p < 2; p++) {
        #pragma unroll
        for (int u = 0; u < 4; u++) {
            int row = lrow + u*32;
            cp_async16(As + p*GSTG + row*GST + lcol, A + (size_t)(m0+row)*DM + p*64 + lcol);
            cp_async16(Bs + p*GSTG + row*GST + lcol, B + (size_t)(n0+row)*DM + p*64 + lcol);
        }
        CP_COMMIT();
    }

    #pragma unroll 1
    for (int s = 0; s < NCH; s++) {
        const int st = s % NSTG;
        if (s + 1 < NCH) { CP_WAIT1(); } else { CP_WAIT0(); }
        __syncthreads();
        if (s + 2 < NCH) {
            const int nst = (s + 2) % NSTG;
            const int k0  = (s + 2) * 64;
            #pragma unroll
            for (int u = 0; u < 4; u++) {
                int row = lrow + u*32;
                cp_async16(As + nst*GSTG + row*GST + lcol,
                           A + (size_t)(m0+row)*DM + k0 + lcol);
                cp_async16(Bs + nst*GSTG + row*GST + lcol,
                           B + (size_t)(n0+row)*DM + k0 + lcol);
            }
            CP_COMMIT();
        }
        const __half* Ab = As + st*GSTG;
        const __half* Bb = Bs + st*GSTG;
        #pragma unroll
        for (int kk = 0; kk < 4; kk++) {
            unsigned af[2][4];
            #pragma unroll
            for (int mt = 0; mt < 2; mt++) {
                unsigned a = smem_u32(Ab + (wr*32 + mt*16 + (lane & 15))*GST
                                      + kk*16 + (lane >> 4)*8);
                ldsm4(af[mt][0], af[mt][1], af[mt][2], af[mt][3], a);
            }
            #pragma unroll
            for (int cp2 = 0; cp2 < 4; cp2++) {
                unsigned r0, r1, r2, r3;
                int row = wc*64 + cp2*16 + (lane >> 4)*8 + (lane & 7);
                int col = kk*16 + ((lane >> 3) & 1)*8;
                ldsm4(r0, r1, r2, r3, smem_u32(Bb + row*GST + col));
                unsigned bfa[2] = {r0, r1}, bfb[2] = {r2, r3};
                #pragma unroll
                for (int mt = 0; mt < 2; mt++) {
                    mma16816(acc[mt][2*cp2],     af[mt], bfa, acc[mt][2*cp2]);
                    mma16816(acc[mt][2*cp2 + 1], af[mt], bfb, acc[mt][2*cp2 + 1]);
                }
            }
        }
    }

    #pragma unroll
    for (int mt = 0; mt < 2; mt++) {
        int r0 = m0 + wr*32 + mt*16 + (lane >> 2);
        int r1 = r0 + 8;
        int b  = r0 >> 11;
        int sx0 = r0 & (SEQ-1), sx1 = r1 & (SEQ-1);
        #pragma unroll
        for (int c8 = 0; c8 < 8; c8++) {
            int col = n0 + wc*64 + c8*8 + 2*(lane & 3);
            float bia0 = bias[col], bia1 = bias[col+1];
            float v0 = (acc[mt][c8][0] + bia0) * scale;
            float v1 = (acc[mt][c8][1] + bia1) * scale;
            float v2 = (acc[mt][c8][2] + bia0) * scale;
            float v3 = (acc[mt][c8][3] + bia1) * scale;
            if (mode == 0) {
                int h = col >> 6, dh = col & (DH-1);
                __half2* p0 = (__half2*)&dsth[(size_t)((b*NH + h)*SEQ + sx0)*DH + dh];
                __half2* p1 = (__half2*)&dsth[(size_t)((b*NH + h)*SEQ + sx1)*DH + dh];
                *p0 = __floats2half2_rn(v0, v1);
                *p1 = __floats2half2_rn(v2, v3);
            } else {
                *(float2*)&dstf[(size_t)r0*DM + col] = make_float2(v0, v1);
                *(float2*)&dstf[(size_t)r1*DM + col] = make_float2(v2, v3);
            }
        }
    }
}

// ---------------- attention: split-K warpgroups, grid 1024 (98.8% waves) ------
// CTA = 128 q-rows x one (b,h). Warpgroup 0 (warps 0-3) handles keys 0..1023,
// warpgroup 1 keys 1024..2047; each warp owns 32 q-rows (mt=2 K/V-ldsm reuse,
// the R11 shape). Per-wg double-buffered K/V + mask, named-barrier sync.
// Epilogue: wg1 dumps O-partials + rowsums to smem; wg0 combines + normalizes.
#define TS 64
#define NTH 16                    // tiles per warpgroup (SEQ/2/TS)
#define AST 72
// smem halves layout: Q[0,9216) | wg KV: 8 bufs x 4608 | msk floats | pad
#define OFF_WKV 9216
#define KVBUF 4608                // one 64x72 half tile
#define OFF_MSK (OFF_WKV + 8*KVBUF)            // halves; floats from here
#define ATT_SMEM_BYTES 120000                  // >113.5KB -> 1 CTA/SM

__global__ __launch_bounds__(256, 1)
void attn_kernel(const int* __restrict__ mask)
{
    extern __shared__ __half smh[];
    __half* Qs = smh;

    const int tid  = threadIdx.x;
    const int w    = tid >> 5;
    const int lane = tid & 31;
    const int wg   = w >> 2;             // 0/1: key-half
    const int ww   = w & 3;              // warp within group
    const int wtid = tid & 127;
    const int bh   = blockIdx.y;
    const int b    = bh >> 4;
    const int h    = bh & (NH-1);
    const int q0   = blockIdx.x * 128;
    const int kbase = wg * (SEQ/2);

    __half* Kw = smh + OFF_WKV + wg*4*KVBUF;        // 2 K stages
    __half* Vw = Kw + 2*KVBUF;                      // 2 V stages
    float*  mskw = (float*)(smh + OFF_MSK) + wg*128; // 2 stages x 64

    const __half* qg  = g_q + (size_t)(bh*SEQ + q0) * DH;
    const __half* kgb = g_k + ((size_t)bh*SEQ + kbase) * DH;
    const __half* vgb = g_v + ((size_t)bh*SEQ + kbase) * DH;

    // prologue: whole CTA loads Q; each wg loads its K/V tile 0
    #pragma unroll
    for (int u = 0; u < 4; u++) {
        int c = tid + u*256;
        int row = c >> 3, col = (c & 7) * 8;
        cp_async16(Qs + row*AST + col, qg + row*DH + col);
    }
    #pragma unroll
    for (int u = 0; u < 4; u++) {
        int c = wtid + u*128;               // 0..511
        int row = c >> 3, col = (c & 7) * 8;
        cp_async16(Kw + row*AST + col, kgb + row*DH + col);
        cp_async16(Vw + row*AST + col, vgb + row*DH + col);
    }
    CP_COMMIT();
    if (wtid < 64)
        mskw[wtid] = (mask[b*SEQ + kbase + wtid] != 0) ? 1.0f : 0.0f;

    CP_WAIT0();
    __syncthreads();

    // Q fragments (both wgs load the same rows; different key halves)
    unsigned qa[2][4][4];
    #pragma unroll
    for (int mt = 0; mt < 2; mt++)
        #pragma unroll
        for (int kd = 0; kd < 4; kd++) {
            unsigned a = smem_u32(Qs + (ww*32 + mt*16 + (lane & 15))*AST
                                  + kd*16 + (lane >> 4)*8);
            ldsm4(qa[mt][kd][0], qa[mt][kd][1], qa[mt][kd][2], qa[mt][kd][3], a);
        }

    float oacc[2][8][4];
    #pragma unroll
    for (int mt = 0; mt < 2; mt++)
        #pragma unroll
        for (int i = 0; i < 8; i++)
            #pragma unroll
            for (int j = 0; j < 4; j++) oacc[mt][i][j] = 0.0f;
    float run0[2] = {0.0f, 0.0f}, run1[2] = {0.0f, 0.0f};

    const int ksrow = (lane >> 4)*8 + (lane & 7);
    const int kscol = ((lane >> 3) & 1)*8;

    #pragma unroll 1
    for (int t = 0; t < NTH; t++) {
        const int buf = t & 1;
        if (t > 0) {
            CP_WAIT0();
            BAR_SYNC(1 + wg);                // wg-local barrier
        }
        if (t + 1 < NTH) {
            const int nb = buf ^ 1;
            const __half* kp = kgb + (size_t)(t+1)*TS*DH;
            const __half* vp = vgb + (size_t)(t+1)*TS*DH;
            #pragma unroll
            for (int u = 0; u < 4; u++) {
                int c = wtid + u*128;
                int row = c >> 3, col = (c & 7) * 8;
                cp_async16(Kw + nb*KVBUF + row*AST + col, kp + row*DH + col);
                cp_async16(Vw + nb*KVBUF + row*AST + col, vp + row*DH + col);
            }
            CP_COMMIT();
            if (wtid < 64)
                mskw[nb*64 + wtid] =
                    (mask[b*SEQ + kbase + (t+1)*TS + wtid] != 0) ? 1.0f : 0.0f;
        }

        const __half* Kb = Kw + buf*KVBUF;
        const __half* Vb = Vw + buf*KVBUF;
        const float*  mk = mskw + buf*64;

        // chunked S/softmax/PV (R11 structure)
        float scb[2][2][2][4];   // [j&1][mt][hh][4]

        #pragma unroll
        for (int mt = 0; mt < 2; mt++)
            #pragma unroll
            for (int hh = 0; hh < 2; hh++)
                #pragma unroll
                for (int e = 0; e < 4; e++) scb[0][mt][hh][e] = 0.0f;
        #pragma unroll
        for (int kd = 0; kd < 4; kd++) {
            unsigned r0, r1, r2, r3;
            ldsm4(r0, r1, r2, r3, smem_u32(Kb + ksrow*AST + kd*16 + kscol));
            unsigned bfa[2] = {r0, r1}, bfb[2] = {r2, r3};
            #pragma unroll
            for (int mt = 0; mt < 2; mt++) {
                mma16816(scb[0][mt][0], qa[mt][kd], bfa, scb[0][mt][0]);
                mma16816(scb[0][mt][1], qa[mt][kd], bfb, scb[0][mt][1]);
            }
        }

        #pragma unroll
        for (int j = 0; j < 4; j++) {
            const int cur = j & 1, nxt = cur ^ 1;
            if (j < 3) {
                #pragma unroll
                for (int mt = 0; mt < 2; mt++)
                    #pragma unroll
                    for (int hh = 0; hh < 2; hh++)
                        #pragma unroll
                        for (int e = 0; e < 4; e++) scb[nxt][mt][hh][e] = 0.0f;
                #pragma unroll
                for (int kd = 0; kd < 4; kd++) {
                    unsigned r0, r1, r2, r3;
                    ldsm4(r0, r1, r2, r3,
                          smem_u32(Kb + ((j+1)*16 + ksrow)*AST + kd*16 + kscol));
                    unsigned bfa[2] = {r0, r1}, bfb[2] = {r2, r3};
                    #pragma unroll
                    for (int mt = 0; mt < 2; mt++) {
                        mma16816(scb[nxt][mt][0], qa[mt][kd], bfa, scb[nxt][mt][0]);
                        mma16816(scb[nxt][mt][1], qa[mt][kd], bfb, scb[nxt][mt][1]);
                    }
                }
            }

            unsigned pa[2][4];
            #pragma unroll
            for (int mt = 0; mt < 2; mt++) {
                #pragma unroll
                for (int hh = 0; hh < 2; hh++) {
                    int c8 = 2*j + hh;
                    float m0 = mk[c8*8 + 2*(lane & 3)];
                    float m1 = mk[c8*8 + 2*(lane & 3) + 1];
                    float p0 = ex2(scb[cur][mt][hh][0]) * m0;
                    float p1 = ex2(scb[cur][mt][hh][1]) * m1;
                    float p2 = ex2(scb[cur][mt][hh][2]) * m0;
                    float p3 = ex2(scb[cur][mt][hh][3]) * m1;
                    __half2 h01 = __floats2half2_rn(p0, p1);
                    __half2 h23 = __floats2half2_rn(p2, p3);
                    pa[mt][hh*2    ] = *(unsigned*)&h01;
                    pa[mt][hh*2 + 1] = *(unsigned*)&h23;
                    float2 f01 = __half22float2(h01);   // sum exactly what PV sees
                    float2 f23 = __half22float2(h23);
                    run0[mt] += f01.x + f01.y;
                    run1[mt] += f23.x + f23.y;
                }
            }

            #pragma unroll
            for (int cp2 = 0; cp2 < 4; cp2++) {
                unsigned r0, r1, r2, r3;
                int row = j*16 + (lane & 15);
                int col = cp2*16 + (lane >> 4)*8;
                ldsm4t(r0, r1, r2, r3, smem_u32(Vb + row*AST + col));
                unsigned bfa[2] = {r0, r1}, bfb[2] = {r2, r3};
                #pragma unroll
                for (int mt = 0; mt < 2; mt++) {
                    mma16816(oacc[mt][2*cp2],     pa[mt], bfa, oacc[mt][2*cp2]);
                    mma16816(oacc[mt][2*cp2 + 1], pa[mt], bfb, oacc[mt][2*cp2 + 1]);
                }
            }
        }
    }

    // quad-reduce rowsums (both wgs)
    #pragma unroll
    for (int mt = 0; mt < 2; mt++) {
        run0[mt] += __shfl_xor_sync(0xffffffffu, run0[mt], 1);
        run0[mt] += __shfl_xor_sync(0xffffffffu, run0[mt], 2);
        run1[mt] += __shfl_xor_sync(0xffffffffu, run1[mt], 1);
        run1[mt] += __shfl_xor_sync(0xffffffffu, run1[mt], 2);
    }

    // combine: wg1 dumps partials into smem (overlaps wg0's dead K/V bufs)
    float* op = (float*)(smh + OFF_WKV);   // 128x64 fp32 = 32KB
    float* rs = op + 128*64;               // 128 fp32
    __syncthreads();                       // both wgs done with K/V reads
    if (wg == 1) {
        #pragma unroll
        for (int mt = 0; mt < 2; mt++) {
            int r0 = ww*32 + mt*16 + (lane >> 2);
            int r1 = r0 + 8;
            #pragma unroll
            for (int c8 = 0; c8 < 8; c8++) {
                int col = c8*8 + 2*(lane & 3);
                *(float2*)&op[r0*64 + col] = make_float2(oacc[mt][c8][0], oacc[mt][c8][1]);
                *(float2*)&op[r1*64 + col] = make_float2(oacc[mt][c8][2], oacc[mt][c8][3]);
            }
            if ((lane & 3) == 0) { rs[r0] = run0[mt]; rs[r1] = run1[mt]; }
        }
    }
    __syncthreads();
    if (wg == 0) {
        #pragma unroll
        for (int mt = 0; mt < 2; mt++) {
            int r0 = ww*32 + mt*16 + (lane >> 2);
            int r1 = r0 + 8;
            float inv0 = 1.0f / (run0[mt] + rs[r0]);
            float inv1 = 1.0f / (run1[mt] + rs[r1]);
            __half* base0 = g_ctx + (size_t)(b*SEQ + q0 + r0)*DM + h*DH;
            __half* base1 = g_ctx + (size_t)(b*SEQ + q0 + r1)*DM + h*DH;
            #pragma unroll
            for (int c8 = 0; c8 < 8; c8++) {
                int col = c8*8 + 2*(lane & 3);
                float2 w0 = *(float2*)&op[r0*64 + col];
                float2 w1 = *(float2*)&op[r1*64 + col];
                __half2 v01 = __floats2half2_rn((oacc[mt][c8][0] + w0.x)*inv0,
                                                (oacc[mt][c8][1] + w0.y)*inv0);
                __half2 v23 = __floats2half2_rn((oacc[mt][c8][2] + w1.x)*inv1,
                                                (oacc[mt][c8][3] + w1.y)*inv1);
                *(__half2*)(base0 + col) = v01;
                *(__half2*)(base1 + col) = v23;
            }
        }
    }
}

// ---------------- launch ------------------------------------------------------
extern "C" void kernel_launch(void* const* d_in, const int* in_sizes, int n_in,
                              void* d_out, int out_size)
{
    const float* Q    = (const float*)d_in[0];
    const float* K    = (const float*)d_in[1];
    const float* V    = (const float*)d_in[2];
    const int*   mask = (const int*)  d_in[3];
    const float* bq   = (const float*)d_in[5];
    const float* bk   = (const float*)d_in[7];
    const float* bv   = (const float*)d_in[9];
    const float* bo   = (const float*)d_in[11];

    cudaFuncSetAttribute(gemm_nt, cudaFuncAttributeMaxDynamicSharedMemorySize,
                         GEMM_SMEM_BYTES);
    cudaFuncSetAttribute(attn_kernel, cudaFuncAttributeMaxDynamicSharedMemorySize,
                         ATT_SMEM_BYTES);

    cvt_acts<<<dim3(MTOT*DM/4/256, 3), 256>>>((const float4*)Q, (const float4*)K,
                                              (const float4*)V);
    cvt_w<<<dim3(DM*DM/4/256, 4), 256>>>((const float4*)d_in[4], (const float4*)d_in[6],
                                         (const float4*)d_in[8], (const float4*)d_in[10]);

    gemm_nt<<<dim3(DM/128, MTOT/128, 3), 256, GEMM_SMEM_BYTES>>>(bq, bk, bv, 0, nullptr);

    attn_kernel<<<dim3(SEQ/128, BSZ*NH), 256, ATT_SMEM_BYTES>>>(mask);

    gemm_nt<<<dim3(DM/128, MTOT/128, 1), 256, GEMM_SMEM_BYTES>>>(bo, nullptr, nullptr,
                                                                 1, (float*)d_out);
}

// round 15
// speedup vs baseline: 1.2769x; 1.2437x over previous
#include <cuda_runtime.h>
#include <cuda_fp16.h>
#include <cstdint>

#define BSZ 4
#define SEQ 2048
#define DM 1024
#define NH 16
#define DH 64
#define MTOT (BSZ*SEQ)   // 8192

// ---------------- device scratch --------------------------------------------
__device__ __half g_xq[MTOT*DM];
__device__ __half g_xk[MTOT*DM];
__device__ __half g_xv[MTOT*DM];
__device__ __half g_wq[DM*DM];
__device__ __half g_wk[DM*DM];
__device__ __half g_wv[DM*DM];
__device__ __half g_wo[DM*DM];
__device__ __half g_q[MTOT*DM];   // (b,h,s,d) fp16, pre-scaled by log2e/8
__device__ __half g_k[MTOT*DM];
__device__ __half g_v[MTOT*DM];
__device__ __half g_ctx[MTOT*DM]; // (b,s,dmodel)
__device__ int    g_cidx[BSZ*SEQ];   // per-batch compacted unmasked key ids
__device__ int    g_cnt[BSZ];        // per-batch count

// ---------------- asm helpers -------------------------------------------------
__device__ __forceinline__ unsigned smem_u32(const void* p) {
    return (unsigned)__cvta_generic_to_shared(p);
}
__device__ __forceinline__ void cp_async16(void* smem, const void* gmem) {
    unsigned s = smem_u32(smem);
    asm volatile("cp.async.cg.shared.global [%0], [%1], 16;\n" :: "r"(s), "l"(gmem));
}
#define CP_COMMIT() asm volatile("cp.async.commit_group;\n" ::: "memory")
#define CP_WAIT0()  asm volatile("cp.async.wait_group 0;\n" ::: "memory")
#define CP_WAIT1()  asm volatile("cp.async.wait_group 1;\n" ::: "memory")

__device__ __forceinline__ void ldsm4(unsigned& r0, unsigned& r1, unsigned& r2,
                                      unsigned& r3, unsigned a) {
    asm volatile("ldmatrix.sync.aligned.m8n8.x4.shared.b16 {%0,%1,%2,%3}, [%4];"
                 : "=r"(r0), "=r"(r1), "=r"(r2), "=r"(r3) : "r"(a));
}
__device__ __forceinline__ void ldsm4t(unsigned& r0, unsigned& r1, unsigned& r2,
                                       unsigned& r3, unsigned a) {
    asm volatile("ldmatrix.sync.aligned.m8n8.x4.trans.shared.b16 {%0,%1,%2,%3}, [%4];"
                 : "=r"(r0), "=r"(r1), "=r"(r2), "=r"(r3) : "r"(a));
}
__device__ __forceinline__ void mma16816(float* d, const unsigned* a,
                                         const unsigned* b, const float* c) {
    asm volatile("mma.sync.aligned.m16n8k16.row.col.f32.f16.f16.f32 "
                 "{%0,%1,%2,%3}, {%4,%5,%6,%7}, {%8,%9}, {%10,%11,%12,%13};"
                 : "=f"(d[0]), "=f"(d[1]), "=f"(d[2]), "=f"(d[3])
                 : "r"(a[0]), "r"(a[1]), "r"(a[2]), "r"(a[3]),
                   "r"(b[0]), "r"(b[1]),
                   "f"(c[0]), "f"(c[1]), "f"(c[2]), "f"(c[3]));
}
__device__ __forceinline__ float ex2(float x) {
    float r; asm("ex2.approx.f32 %0, %1;" : "=f"(r) : "f"(x)); return r;
}

// ---------------- fp32 -> fp16 conversion ------------------------------------
__global__ void cvt_acts(const float4* __restrict__ q, const float4* __restrict__ k,
                         const float4* __restrict__ v) {
    const float4* src = (blockIdx.y == 0) ? q : (blockIdx.y == 1) ? k : v;
    __half2* dst = (blockIdx.y == 0) ? (__half2*)g_xq
                 : (blockIdx.y == 1) ? (__half2*)g_xk : (__half2*)g_xv;
    int i = blockIdx.x * blockDim.x + threadIdx.x;
    float4 f = src[i];
    dst[2*i]   = __floats2half2_rn(f.x, f.y);
    dst[2*i+1] = __floats2half2_rn(f.z, f.w);
}
__global__ void cvt_w(const float4* __restrict__ wq, const float4* __restrict__ wk,
                      const float4* __restrict__ wv, const float4* __restrict__ wo) {
    const float4* src = (blockIdx.y == 0) ? wq : (blockIdx.y == 1) ? wk
                      : (blockIdx.y == 2) ? wv : wo;
    __half2* dst = (blockIdx.y == 0) ? (__half2*)g_wq : (blockIdx.y == 1) ? (__half2*)g_wk
                 : (blockIdx.y == 2) ? (__half2*)g_wv : (__half2*)g_wo;
    int i = blockIdx.x * blockDim.x + threadIdx.x;
    float4 f = src[i];
    dst[2*i]   = __floats2half2_rn(f.x, f.y);
    dst[2*i+1] = __floats2half2_rn(f.z, f.w);
}

// ---------------- compacted key-index builder (one block per batch) -----------
__global__ void build_idx(const int* __restrict__ mask) {
    __shared__ int wsum[8];
    const int b   = blockIdx.x;
    const int tid = threadIdx.x;          // 256 threads, 8 keys each
    const int lane = tid & 31, w = tid >> 5;
    int m[8], loc = 0;
    #pragma unroll
    for (int i = 0; i < 8; i++) {
        m[i] = (mask[b*SEQ + tid*8 + i] != 0);
        loc += m[i];
    }
    int scan = loc;                       // warp inclusive scan
    #pragma unroll
    for (int o = 1; o < 32; o <<= 1) {
        int v = __shfl_up_sync(0xffffffffu, scan, o);
        if (lane >= o) scan += v;
    }
    if (lane == 31) wsum[w] = scan;
    __syncthreads();
    if (tid == 0) {
        int a = 0;
        #pragma unroll
        for (int i = 0; i < 8; i++) { int t = wsum[i]; wsum[i] = a; a += t; }
    }
    __syncthreads();
    int pos = scan - loc + wsum[w];       // exclusive prefix
    #pragma unroll
    for (int i = 0; i < 8; i++) {
        if (m[i]) g_cidx[b*SEQ + pos++] = tid*8 + i;
    }
    if (tid == 255) g_cnt[b] = pos;       // last thread's inclusive total
}

// ---------------- NT GEMM: 3-stage cp.async, 2 CTAs/SM (R11, unchanged) ------
#define GST 72
#define GSTG (128*GST)
#define NSTG 3
#define GEMM_SMEM_BYTES (2*NSTG*GSTG*2)   // 110592 B -> 2 CTAs/SM

__global__ __launch_bounds__(256, 2)
void gemm_nt(const float* __restrict__ b0, const float* __restrict__ b1,
             const float* __restrict__ b2, int mode, float* __restrict__ dstf)
{
    extern __shared__ __half smh[];
    __half* As = smh;
    __half* Bs = smh + NSTG*GSTG;

    const int z = blockIdx.z;
    const __half* __restrict__ A;
    const __half* __restrict__ B;
    const float* __restrict__ bias;
    __half* dsth;
    float scale;
    if (mode == 0) {
        A = (z == 0) ? g_xq : (z == 1) ? g_xk : g_xv;
        B = (z == 0) ? g_wq : (z == 1) ? g_wk : g_wv;
        bias = (z == 0) ? b0 : (z == 1) ? b1 : b2;
        dsth = (z == 0) ? g_q : (z == 1) ? g_k : g_v;
        scale = (z == 0) ? 0.125f * 1.44269504088896f : 1.0f;
    } else {
        A = g_ctx; B = g_wo; bias = b0; dsth = nullptr; scale = 1.0f;
    }

    const int tid  = threadIdx.x;
    const int w    = tid >> 5;
    const int lane = tid & 31;
    const int wr   = w >> 1;
    const int wc   = w & 1;
    const int m0   = blockIdx.y * 128;
    const int n0   = blockIdx.x * 128;

    float acc[2][8][4];
    #pragma unroll
    for (int mt = 0; mt < 2; mt++)
        #pragma unroll
        for (int i = 0; i < 8; i++)
            #pragma unroll
            for (int j = 0; j < 4; j++) acc[mt][i][j] = 0.0f;

    const int NCH = DM / 64;
    const int lrow = tid >> 3, lcol = (tid & 7) * 8;

    #pragma unroll
    for (int p = 0; p < 2; p++) {
        #pragma unroll
        for (int u = 0; u < 4; u++) {
            int row = lrow + u*32;
            cp_async16(As + p*GSTG + row*GST + lcol, A + (size_t)(m0+row)*DM + p*64 + lcol);
            cp_async16(Bs + p*GSTG + row*GST + lcol, B + (size_t)(n0+row)*DM + p*64 + lcol);
        }
        CP_COMMIT();
    }

    #pragma unroll 1
    for (int s = 0; s < NCH; s++) {
        const int st = s % NSTG;
        if (s + 1 < NCH) { CP_WAIT1(); } else { CP_WAIT0(); }
        __syncthreads();
        if (s + 2 < NCH) {
            const int nst = (s + 2) % NSTG;
            const int k0  = (s + 2) * 64;
            #pragma unroll
            for (int u = 0; u < 4; u++) {
                int row = lrow + u*32;
                cp_async16(As + nst*GSTG + row*GST + lcol,
                           A + (size_t)(m0+row)*DM + k0 + lcol);
                cp_async16(Bs + nst*GSTG + row*GST + lcol,
                           B + (size_t)(n0+row)*DM + k0 + lcol);
            }
            CP_COMMIT();
        }
        const __half* Ab = As + st*GSTG;
        const __half* Bb = Bs + st*GSTG;
        #pragma unroll
        for (int kk = 0; kk < 4; kk++) {
            unsigned af[2][4];
            #pragma unroll
            for (int mt = 0; mt < 2; mt++) {
                unsigned a = smem_u32(Ab + (wr*32 + mt*16 + (lane & 15))*GST
                                      + kk*16 + (lane >> 4)*8);
                ldsm4(af[mt][0], af[mt][1], af[mt][2], af[mt][3], a);
            }
            #pragma unroll
            for (int cp2 = 0; cp2 < 4; cp2++) {
                unsigned r0, r1, r2, r3;
                int row = wc*64 + cp2*16 + (lane >> 4)*8 + (lane & 7);
                int col = kk*16 + ((lane >> 3) & 1)*8;
                ldsm4(r0, r1, r2, r3, smem_u32(Bb + row*GST + col));
                unsigned bfa[2] = {r0, r1}, bfb[2] = {r2, r3};
                #pragma unroll
                for (int mt = 0; mt < 2; mt++) {
                    mma16816(acc[mt][2*cp2],     af[mt], bfa, acc[mt][2*cp2]);
                    mma16816(acc[mt][2*cp2 + 1], af[mt], bfb, acc[mt][2*cp2 + 1]);
                }
            }
        }
    }

    #pragma unroll
    for (int mt = 0; mt < 2; mt++) {
        int r0 = m0 + wr*32 + mt*16 + (lane >> 2);
        int r1 = r0 + 8;
        int b  = r0 >> 11;
        int sx0 = r0 & (SEQ-1), sx1 = r1 & (SEQ-1);
        #pragma unroll
        for (int c8 = 0; c8 < 8; c8++) {
            int col = n0 + wc*64 + c8*8 + 2*(lane & 3);
            float bia0 = bias[col], bia1 = bias[col+1];
            float v0 = (acc[mt][c8][0] + bia0) * scale;
            float v1 = (acc[mt][c8][1] + bia1) * scale;
            float v2 = (acc[mt][c8][2] + bia0) * scale;
            float v3 = (acc[mt][c8][3] + bia1) * scale;
            if (mode == 0) {
                int h = col >> 6, dh = col & (DH-1);
                __half2* p0 = (__half2*)&dsth[(size_t)((b*NH + h)*SEQ + sx0)*DH + dh];
                __half2* p1 = (__half2*)&dsth[(size_t)((b*NH + h)*SEQ + sx1)*DH + dh];
                *p0 = __floats2half2_rn(v0, v1);
                *p1 = __floats2half2_rn(v2, v3);
            } else {
                *(float2*)&dstf[(size_t)r0*DM + col] = make_float2(v0, v1);
                *(float2*)&dstf[(size_t)r1*DM + col] = make_float2(v2, v3);
            }
        }
    }
}

// ---------------- attention: compacted keys (skip masked), R11 shape ----------
// 256 q-rows/CTA, warp owns 32 rows (mt=2 K/V-ldsm reuse). K/V rows gathered
// via per-batch compacted index list; only ~cnt/64 tiles processed (~half).
// Tail-tile validity takes the old mask's role. fp32-ex2 chunked softmax.
#define TS 64
#define AST 72
#define QROWS 256
#define OFF_KS (QROWS*AST)
#define OFF_VS (OFF_KS + 2*TS*AST)
#define OFF_MSK (OFF_VS + 2*TS*AST)            // floats from here
#define ATT_SMEM_BYTES (OFF_MSK*2 + 2*64*4)

__global__ __launch_bounds__(256, 1)
void attn_kernel()
{
    extern __shared__ __half smh[];
    __half* Qs = smh;
    __half* Ks = smh + OFF_KS;
    __half* Vs = smh + OFF_VS;
    float*  msk = (float*)(smh + OFF_MSK);

    const int tid  = threadIdx.x;
    const int w    = tid >> 5;
    const int lane = tid & 31;
    const int bh   = blockIdx.y;
    const int b    = bh >> 4;
    const int h    = bh & (NH-1);
    const int q0   = blockIdx.x * QROWS;

    const __half* qg  = g_q + (size_t)(bh*SEQ + q0) * DH;
    const __half* kgb = g_k + (size_t)bh * SEQ * DH;
    const __half* vgb = g_v + (size_t)bh * SEQ * DH;
    const int*    cid = g_cidx + b*SEQ;
    const int     cnt = g_cnt[b];
    const int  ntiles = max(1, (cnt + TS - 1) / TS);

    // prefetch Q + gathered K/V tile 0
    #pragma unroll
    for (int u = 0; u < 8; u++) {
        int c = tid + u*256;
        int row = c >> 3, col = (c & 7) * 8;
        cp_async16(Qs + row*AST + col, qg + row*DH + col);
    }
    #pragma unroll
    for (int u = 0; u < 2; u++) {
        int c = tid + u*256;
        int row = c >> 3, col = (c & 7) * 8;
        int gi = (row < cnt) ? cid[row] : 0;
        cp_async16(Ks + row*AST + col, kgb + (size_t)gi*DH + col);
        cp_async16(Vs + row*AST + col, vgb + (size_t)gi*DH + col);
    }
    CP_COMMIT();
    if (tid < 64) msk[tid] = (tid < cnt) ? 1.0f : 0.0f;

    CP_WAIT0();
    __syncthreads();

    unsigned qa[2][4][4];
    #pragma unroll
    for (int mt = 0; mt < 2; mt++)
        #pragma unroll
        for (int kd = 0; kd < 4; kd++) {
            unsigned a = smem_u32(Qs + (w*32 + mt*16 + (lane & 15))*AST
                                  + kd*16 + (lane >> 4)*8);
            ldsm4(qa[mt][kd][0], qa[mt][kd][1], qa[mt][kd][2], qa[mt][kd][3], a);
        }

    float oacc[2][8][4];
    #pragma unroll
    for (int mt = 0; mt < 2; mt++)
        #pragma unroll
        for (int i = 0; i < 8; i++)
            #pragma unroll
            for (int j = 0; j < 4; j++) oacc[mt][i][j] = 0.0f;
    float run0[2] = {0.0f, 0.0f}, run1[2] = {0.0f, 0.0f};

    const int ksrow = (lane >> 4)*8 + (lane & 7);
    const int kscol = ((lane >> 3) & 1)*8;

    #pragma unroll 1
    for (int t = 0; t < ntiles; t++) {
        const int buf = t & 1;
        if (t > 0) {
            CP_WAIT0();
            __syncthreads();
        }
        if (t + 1 < ntiles) {
            const int nb = buf ^ 1;
            const int k0 = (t + 1) * TS;
            #pragma unroll
            for (int u = 0; u < 2; u++) {
                int c = tid + u*256;
                int row = c >> 3, col = (c & 7) * 8;
                int slot = k0 + row;
                int gi = (slot < cnt) ? cid[slot] : 0;
                cp_async16(Ks + nb*TS*AST + row*AST + col, kgb + (size_t)gi*DH + col);
                cp_async16(Vs + nb*TS*AST + row*AST + col, vgb + (size_t)gi*DH + col);
            }
            CP_COMMIT();
            if (tid < 64)
                msk[nb*64 + tid] = (k0 + tid < cnt) ? 1.0f : 0.0f;
        }

        const __half* Kb = Ks + buf*TS*AST;
        const __half* Vb = Vs + buf*TS*AST;
        const float*  mk = msk + buf*64;

        // chunk-pipelined S/softmax/PV (R11 structure)
        float scb[2][2][2][4];   // [j&1][mt][hh][4]

        #pragma unroll
        for (int mt = 0; mt < 2; mt++)
            #pragma unroll
            for (int hh = 0; hh < 2; hh++)
                #pragma unroll
                for (int e = 0; e < 4; e++) scb[0][mt][hh][e] = 0.0f;
        #pragma unroll
        for (int kd = 0; kd < 4; kd++) {
            unsigned r0, r1, r2, r3;
            ldsm4(r0, r1, r2, r3, smem_u32(Kb + ksrow*AST + kd*16 + kscol));
            unsigned bfa[2] = {r0, r1}, bfb[2] = {r2, r3};
            #pragma unroll
            for (int mt = 0; mt < 2; mt++) {
                mma16816(scb[0][mt][0], qa[mt][kd], bfa, scb[0][mt][0]);
                mma16816(scb[0][mt][1], qa[mt][kd], bfb, scb[0][mt][1]);
            }
        }

        #pragma unroll
        for (int j = 0; j < 4; j++) {
            const int cur = j & 1, nxt = cur ^ 1;
            if (j < 3) {
                #pragma unroll
                for (int mt = 0; mt < 2; mt++)
                    #pragma unroll
                    for (int hh = 0; hh < 2; hh++)
                        #pragma unroll
                        for (int e = 0; e < 4; e++) scb[nxt][mt][hh][e] = 0.0f;
                #pragma unroll
                for (int kd = 0; kd < 4; kd++) {
                    unsigned r0, r1, r2, r3;
                    ldsm4(r0, r1, r2, r3,
                          smem_u32(Kb + ((j+1)*16 + ksrow)*AST + kd*16 + kscol));
                    unsigned bfa[2] = {r0, r1}, bfb[2] = {r2, r3};
                    #pragma unroll
                    for (int mt = 0; mt < 2; mt++) {
                        mma16816(scb[nxt][mt][0], qa[mt][kd], bfa, scb[nxt][mt][0]);
                        mma16816(scb[nxt][mt][1], qa[mt][kd], bfb, scb[nxt][mt][1]);
                    }
                }
            }

            unsigned pa[2][4];
            #pragma unroll
            for (int mt = 0; mt < 2; mt++) {
                #pragma unroll
                for (int hh = 0; hh < 2; hh++) {
                    int c8 = 2*j + hh;
                    float m0 = mk[c8*8 + 2*(lane & 3)];
                    float m1 = mk[c8*8 + 2*(lane & 3) + 1];
                    float p0 = ex2(scb[cur][mt][hh][0]) * m0;
                    float p1 = ex2(scb[cur][mt][hh][1]) * m1;
                    float p2 = ex2(scb[cur][mt][hh][2]) * m0;
                    float p3 = ex2(scb[cur][mt][hh][3]) * m1;
                    __half2 h01 = __floats2half2_rn(p0, p1);
                    __half2 h23 = __floats2half2_rn(p2, p3);
                    pa[mt][hh*2    ] = *(unsigned*)&h01;
                    pa[mt][hh*2 + 1] = *(unsigned*)&h23;
                    float2 f01 = __half22float2(h01);   // sum exactly what PV sees
                    float2 f23 = __half22float2(h23);
                    run0[mt] += f01.x + f01.y;
                    run1[mt] += f23.x + f23.y;
                }
            }

            #pragma unroll
            for (int cp2 = 0; cp2 < 4; cp2++) {
                unsigned r0, r1, r2, r3;
                int row = j*16 + (lane & 15);
                int col = cp2*16 + (lane >> 4)*8;
                ldsm4t(r0, r1, r2, r3, smem_u32(Vb + row*AST + col));
                unsigned bfa[2] = {r0, r1}, bfb[2] = {r2, r3};
                #pragma unroll
                for (int mt = 0; mt < 2; mt++) {
                    mma16816(oacc[mt][2*cp2],     pa[mt], bfa, oacc[mt][2*cp2]);
                    mma16816(oacc[mt][2*cp2 + 1], pa[mt], bfb, oacc[mt][2*cp2 + 1]);
                }
            }
        }
    }

    // quad-reduce rowsums, normalize + store
    #pragma unroll
    for (int mt = 0; mt < 2; mt++) {
        run0[mt] += __shfl_xor_sync(0xffffffffu, run0[mt], 1);
        run0[mt] += __shfl_xor_sync(0xffffffffu, run0[mt], 2);
        run1[mt] += __shfl_xor_sync(0xffffffffu, run1[mt], 1);
        run1[mt] += __shfl_xor_sync(0xffffffffu, run1[mt], 2);
    }
    #pragma unroll
    for (int mt = 0; mt < 2; mt++) {
        float inv0 = 1.0f / run0[mt], inv1 = 1.0f / run1[mt];
        int r0 = q0 + w*32 + mt*16 + (lane >> 2);
        int r1 = r0 + 8;
        __half* base0 = g_ctx + (size_t)(b*SEQ + r0)*DM + h*DH;
        __half* base1 = g_ctx + (size_t)(b*SEQ + r1)*DM + h*DH;
        #pragma unroll
        for (int c8 = 0; c8 < 8; c8++) {
            int col = c8*8 + 2*(lane & 3);
            __half2 v01 = __floats2half2_rn(oacc[mt][c8][0]*inv0, oacc[mt][c8][1]*inv0);
            __half2 v23 = __floats2half2_rn(oacc[mt][c8][2]*inv1, oacc[mt][c8][3]*inv1);
            *(__half2*)(base0 + col) = v01;
            *(__half2*)(base1 + col) = v23;
        }
    }
}

// ---------------- launch ------------------------------------------------------
extern "C" void kernel_launch(void* const* d_in, const int* in_sizes, int n_in,
                              void* d_out, int out_size)
{
    const float* Q    = (const float*)d_in[0];
    const float* K    = (const float*)d_in[1];
    const float* V    = (const float*)d_in[2];
    const int*   mask = (const int*)  d_in[3];
    const float* bq   = (const float*)d_in[5];
    const float* bk   = (const float*)d_in[7];
    const float* bv   = (const float*)d_in[9];
    const float* bo   = (const float*)d_in[11];

    cudaFuncSetAttribute(gemm_nt, cudaFuncAttributeMaxDynamicSharedMemorySize,
                         GEMM_SMEM_BYTES);
    cudaFuncSetAttribute(attn_kernel, cudaFuncAttributeMaxDynamicSharedMemorySize,
                         ATT_SMEM_BYTES);

    cvt_acts<<<dim3(MTOT*DM/4/256, 3), 256>>>((const float4*)Q, (const float4*)K,
                                              (const float4*)V);
    cvt_w<<<dim3(DM*DM/4/256, 4), 256>>>((const float4*)d_in[4], (const float4*)d_in[6],
                                         (const float4*)d_in[8], (const float4*)d_in[10]);
    build_idx<<<BSZ, 256>>>(mask);

    gemm_nt<<<dim3(DM/128, MTOT/128, 3), 256, GEMM_SMEM_BYTES>>>(bq, bk, bv, 0, nullptr);

    attn_kernel<<<dim3(SEQ/QROWS, BSZ*NH), 256, ATT_SMEM_BYTES>>>();

    gemm_nt<<<dim3(DM/128, MTOT/128, 1), 256, GEMM_SMEM_BYTES>>>(bo, nullptr, nullptr,
                                                                 1, (float*)d_out);
}